// round 2
// baseline (speedup 1.0000x reference)
#include <cuda_runtime.h>
#include <math.h>

#define B_    16
#define S_    2048
#define D_    1024
#define H_    16
#define P_    8
#define R_    128      // H_*P_
#define HD_   64
#define SUMN  73
#define NROW  1168     // B_*SUMN
#define NROWP 1280     // padded to 10*128

// ---------------- scratch (static device globals; no allocation) ----------------
__device__ int   g_len[B_];
__device__ float g_q[P_ * D_];
__device__ float g_A[R_ * D_];
__device__ float g_cb[R_];
__device__ float g_sc[(size_t)B_ * R_ * S_];      // scores -> attn (in place)
__device__ float g_cr[(size_t)B_ * R_ * D_];      // ctxRaw [b][r=h*8+p][e]
__device__ float g_ctxp[8][R_ * D_];              // k-split partials for ctx
__device__ float g_ctx[R_ * D_];                  // [m=b*8+p][h*64+d]
__device__ float g_poolp[8][R_ * D_];             // k-split partials for pooled
__device__ float g_pool[R_ * D_];                 // [m=b*8+p][f]
__device__ float g_lnv[(size_t)NROWP * D_];
__device__ float g_lng[(size_t)NROWP * D_];
__device__ float g_vraw[(size_t)NROW * D_];
__device__ float g_graw[(size_t)NROW * D_];
__device__ float g_msk[NROWP];

// ---------------- helpers ----------------
__device__ __forceinline__ float blk_red_sum(float v, float* sh) {
    #pragma unroll
    for (int o = 16; o > 0; o >>= 1) v += __shfl_down_sync(0xffffffffu, v, o);
    int w = threadIdx.x >> 5, l = threadIdx.x & 31;
    __syncthreads();
    if (l == 0) sh[w] = v;
    __syncthreads();
    float r = 0.f;
    #pragma unroll
    for (int i = 0; i < 8; i++) r += sh[i];
    return r;
}

__device__ __forceinline__ float blk_red_max(float v, float* sh) {
    #pragma unroll
    for (int o = 16; o > 0; o >>= 1) v = fmaxf(v, __shfl_down_sync(0xffffffffu, v, o));
    int w = threadIdx.x >> 5, l = threadIdx.x & 31;
    __syncthreads();
    if (l == 0) sh[w] = v;
    __syncthreads();
    float r = -3.4e38f;
    #pragma unroll
    for (int i = 0; i < 8; i++) r = fmaxf(r, sh[i]);
    return r;
}

// ---------------- K0: per-batch valid length (dtype-adaptive: uint8 bool OR int32) ----------------
// valid_mask is a prefix mask. Detect layout from the first 16 bytes:
//   uint8 bool : first min(len0,16) bytes are 1      -> >4 ones when len0 >= 5
//   int32      : one nonzero byte per valid int       -> <=4 ones in first 16 bytes
__global__ void k_len(const void* __restrict__ vmraw) {
    __shared__ int sh[256];
    __shared__ int is_u8;
    const unsigned char* vb = (const unsigned char*)vmraw;
    int b = blockIdx.x;
    if (threadIdx.x == 0) {
        int ones = 0;
        #pragma unroll
        for (int i = 0; i < 16; i++) ones += (vb[i] != 0) ? 1 : 0;
        is_u8 = (ones > 4) ? 1 : 0;
    }
    __syncthreads();
    int c = 0;
    if (is_u8) {
        for (int i = threadIdx.x; i < S_; i += 256)
            c += (vb[(size_t)b * S_ + i] != 0) ? 1 : 0;
    } else {
        const int* vi = (const int*)vmraw;
        for (int i = threadIdx.x; i < S_; i += 256)
            c += (vi[(size_t)b * S_ + i] != 0) ? 1 : 0;
    }
    sh[threadIdx.x] = c;
    __syncthreads();
    for (int o = 128; o > 0; o >>= 1) {
        if (threadIdx.x < o) sh[threadIdx.x] += sh[threadIdx.x + o];
        __syncthreads();
    }
    if (threadIdx.x == 0) g_len[b] = sh[0];
}

// ---------------- K1: q = queries @ Wq^T + bq  (warp per output) ----------------
__global__ void k_q(const float* __restrict__ qry, const float* __restrict__ w,
                    const float* __restrict__ bia) {
    int wid = (blockIdx.x * 256 + threadIdx.x) >> 5;
    int l = threadIdx.x & 31;
    int p = wid >> 10;
    int j = wid & 1023;
    const float* qr = qry + (size_t)p * D_;
    const float* wr = w + (size_t)j * D_;
    float s = 0.f;
    for (int e = l; e < D_; e += 32) s += qr[e] * wr[e];
    #pragma unroll
    for (int o = 16; o > 0; o >>= 1) s += __shfl_down_sync(0xffffffffu, s, o);
    if (l == 0) g_q[p * D_ + j] = s + bia[j];
}

// ---------------- K2: A[r][e] = (1/8) * sum_d q[p][h*64+d] * Wk[h*64+d][e] ----------------
__global__ void k_A(const float* __restrict__ w) {
    int idx = blockIdx.x * 256 + threadIdx.x;   // < 128*1024
    int r = idx >> 10, e = idx & 1023;
    int h = r >> 3, p = r & 7;
    const float* qrow = g_q + p * D_ + h * HD_;
    const float* wr = w + (size_t)(D_ + h * HD_) * D_ + e;
    float s = 0.f;
    #pragma unroll 8
    for (int d = 0; d < HD_; d++) s += qrow[d] * wr[(size_t)d * D_];
    g_A[idx] = 0.125f * s;
}

__global__ void k_cb(const float* __restrict__ bia) {
    int r = threadIdx.x;
    if (r >= R_) return;
    int h = r >> 3, p = r & 7;
    float s = 0.f;
    for (int d = 0; d < HD_; d++) s += g_q[p * D_ + h * HD_ + d] * bia[D_ + h * HD_ + d];
    g_cb[r] = 0.125f * s;
}

// ---------------- K3: scores[b][r][s] = hidden[b][s] . A[r] + cb[r], masked ----------------
__global__ void __launch_bounds__(256, 2) k_scores(const float* __restrict__ hid) {
    const int b = blockIdx.y;
    const int s0 = blockIdx.x * 128;
    const int len = g_len[b];
    const int tid = threadIdx.x;
    if (s0 >= len) {  // whole tile masked: write -1e9 directly
        float4 m4 = make_float4(-1e9f, -1e9f, -1e9f, -1e9f);
        for (int i = tid; i < 128 * 32; i += 256) {
            int r = i >> 5, sq = (i & 31) << 2;
            *(float4*)&g_sc[((size_t)(b * R_ + r)) * S_ + s0 + sq] = m4;
        }
        return;
    }
    __shared__ float As[8][132];   // A over r
    __shared__ float Bs[8][132];   // hidden over s
    float acc[8][8];
    #pragma unroll
    for (int i = 0; i < 8; i++)
        #pragma unroll
        for (int j = 0; j < 8; j++) acc[i][j] = 0.f;
    const float* hb = hid + (size_t)b * S_ * D_;
    const int lr = tid >> 1;
    const int lq = (tid & 1) * 4;
    const int ty = tid >> 4;   // r dir
    const int tx = tid & 15;   // s dir
    for (int k0 = 0; k0 < D_; k0 += 8) {
        float4 av = *(const float4*)&g_A[(size_t)lr * D_ + k0 + lq];
        float4 hv = *(const float4*)&hb[(size_t)(s0 + lr) * D_ + k0 + lq];
        __syncthreads();
        As[lq + 0][lr] = av.x; As[lq + 1][lr] = av.y; As[lq + 2][lr] = av.z; As[lq + 3][lr] = av.w;
        Bs[lq + 0][lr] = hv.x; Bs[lq + 1][lr] = hv.y; Bs[lq + 2][lr] = hv.z; Bs[lq + 3][lr] = hv.w;
        __syncthreads();
        #pragma unroll
        for (int kk = 0; kk < 8; kk++) {
            float a[8], bb[8];
            #pragma unroll
            for (int i = 0; i < 8; i++) a[i] = As[kk][ty * 8 + i];
            #pragma unroll
            for (int j = 0; j < 8; j++) bb[j] = Bs[kk][tx * 8 + j];
            #pragma unroll
            for (int i = 0; i < 8; i++)
                #pragma unroll
                for (int j = 0; j < 8; j++) acc[i][j] = fmaf(a[i], bb[j], acc[i][j]);
        }
    }
    #pragma unroll
    for (int i = 0; i < 8; i++) {
        int r = ty * 8 + i;
        float cb = g_cb[r];
        float o[8];
        #pragma unroll
        for (int j = 0; j < 8; j++) {
            int s = s0 + tx * 8 + j;
            o[j] = (s < len) ? acc[i][j] + cb : -1e9f;
        }
        float* dst = &g_sc[((size_t)(b * R_ + r)) * S_ + s0 + tx * 8];
        *(float4*)dst = make_float4(o[0], o[1], o[2], o[3]);
        *(float4*)(dst + 4) = make_float4(o[4], o[5], o[6], o[7]);
    }
}

// ---------------- K4: softmax over s per (b,r) row, in place ----------------
__global__ void k_softmax() {
    __shared__ float sh[8];
    size_t base = (size_t)blockIdx.x * S_;
    int tid = threadIdx.x;
    float v[8];
    float mx = -3.4e38f;
    #pragma unroll
    for (int i = 0; i < 8; i++) {
        v[i] = g_sc[base + tid + i * 256];
        mx = fmaxf(mx, v[i]);
    }
    float bm = blk_red_max(mx, sh);
    float s = 0.f;
    #pragma unroll
    for (int i = 0; i < 8; i++) { v[i] = expf(v[i] - bm); s += v[i]; }
    float bs = blk_red_sum(s, sh);
    float inv = 1.f / bs;
    #pragma unroll
    for (int i = 0; i < 8; i++) g_sc[base + tid + i * 256] = v[i] * inv;
}

// ---------------- K5: ctxRaw[b][r][e] = sum_s attn[b][r][s] * hidden[b][s][e] ----------------
__global__ void __launch_bounds__(256, 2) k_ctxraw(const float* __restrict__ hid) {
    const int b = blockIdx.y;
    const int e0 = blockIdx.x * 128;
    const int len = g_len[b];
    const int kend = (len + 7) & ~7;   // attn is exactly 0 beyond len
    const int tid = threadIdx.x;
    __shared__ float As[8][132];   // attn over r
    __shared__ float Bs[8][132];   // hidden over e
    float acc[8][8];
    #pragma unroll
    for (int i = 0; i < 8; i++)
        #pragma unroll
        for (int j = 0; j < 8; j++) acc[i][j] = 0.f;
    const float* hb = hid + (size_t)b * S_ * D_;
    const int lr = tid >> 1;
    const int lq = (tid & 1) * 4;
    const int hk = tid >> 5;
    const int he = (tid & 31) * 4;
    const int ty = tid >> 4;
    const int tx = tid & 15;
    for (int k0 = 0; k0 < kend; k0 += 8) {
        float4 av = *(const float4*)&g_sc[((size_t)(b * R_ + lr)) * S_ + k0 + lq];
        float4 hv = *(const float4*)&hb[(size_t)(k0 + hk) * D_ + e0 + he];
        __syncthreads();
        As[lq + 0][lr] = av.x; As[lq + 1][lr] = av.y; As[lq + 2][lr] = av.z; As[lq + 3][lr] = av.w;
        Bs[hk][he + 0] = hv.x; Bs[hk][he + 1] = hv.y; Bs[hk][he + 2] = hv.z; Bs[hk][he + 3] = hv.w;
        __syncthreads();
        #pragma unroll
        for (int kk = 0; kk < 8; kk++) {
            float a[8], bb[8];
            #pragma unroll
            for (int i = 0; i < 8; i++) a[i] = As[kk][ty * 8 + i];
            #pragma unroll
            for (int j = 0; j < 8; j++) bb[j] = Bs[kk][tx * 8 + j];
            #pragma unroll
            for (int i = 0; i < 8; i++)
                #pragma unroll
                for (int j = 0; j < 8; j++) acc[i][j] = fmaf(a[i], bb[j], acc[i][j]);
        }
    }
    #pragma unroll
    for (int i = 0; i < 8; i++) {
        int r = ty * 8 + i;
        float* dst = &g_cr[((size_t)(b * R_ + r)) * D_ + e0 + tx * 8];
        *(float4*)dst = make_float4(acc[i][0], acc[i][1], acc[i][2], acc[i][3]);
        *(float4*)(dst + 4) = make_float4(acc[i][4], acc[i][5], acc[i][6], acc[i][7]);
    }
}

// ---------------- K6: ctx per head (k-split partials) ----------------
// ctx[b][p][h*64+n] = sum_e ctxRaw[b][h*8+p][e] * Wv[h*64+n][e]   (bias added in reduce)
__global__ void k_ctx(const float* __restrict__ w) {
    const int h = blockIdx.x;    // 16
    const int ks = blockIdx.y;   // 8
    const int tid = threadIdx.x;
    __shared__ float As[8][132];  // m = b*8+p
    __shared__ float Bs[8][68];   // n in [0,64)
    float acc[8][4];
    #pragma unroll
    for (int i = 0; i < 8; i++)
        #pragma unroll
        for (int j = 0; j < 4; j++) acc[i][j] = 0.f;
    const int lm = tid >> 1;
    const int lq = (tid & 1) * 4;
    const int ln_ = tid >> 2;        // 0..63
    const int lq2 = (tid & 3) * 2;
    const int ty = tid >> 4;
    const int tx = tid & 15;
    const int bA = lm >> 3, pA = lm & 7;
    const size_t arow = ((size_t)(bA * R_ + h * P_ + pA)) * D_;
    const size_t wrow = (size_t)(2 * D_ + h * HD_ + ln_) * D_;
    for (int k0 = ks * 128; k0 < ks * 128 + 128; k0 += 8) {
        float4 av = *(const float4*)&g_cr[arow + k0 + lq];
        float2 wv = *(const float2*)&w[wrow + k0 + lq2];
        __syncthreads();
        As[lq + 0][lm] = av.x; As[lq + 1][lm] = av.y; As[lq + 2][lm] = av.z; As[lq + 3][lm] = av.w;
        Bs[lq2 + 0][ln_] = wv.x; Bs[lq2 + 1][ln_] = wv.y;
        __syncthreads();
        #pragma unroll
        for (int kk = 0; kk < 8; kk++) {
            float a[8], bb[4];
            #pragma unroll
            for (int i = 0; i < 8; i++) a[i] = As[kk][ty * 8 + i];
            #pragma unroll
            for (int j = 0; j < 4; j++) bb[j] = Bs[kk][tx * 4 + j];
            #pragma unroll
            for (int i = 0; i < 8; i++)
                #pragma unroll
                for (int j = 0; j < 4; j++) acc[i][j] = fmaf(a[i], bb[j], acc[i][j]);
        }
    }
    #pragma unroll
    for (int i = 0; i < 8; i++) {
        int m = ty * 8 + i;
        *(float4*)&g_ctxp[ks][(size_t)m * D_ + h * HD_ + tx * 4] =
            make_float4(acc[i][0], acc[i][1], acc[i][2], acc[i][3]);
    }
}

__global__ void k_ctxred(const float* __restrict__ ipb) {
    int idx = blockIdx.x * 256 + threadIdx.x;   // < 128*1024
    float s = ipb[2 * D_ + (idx & 1023)];
    #pragma unroll
    for (int ks = 0; ks < 8; ks++) s += g_ctxp[ks][idx];
    g_ctx[idx] = s;
}

// ---------------- K7: pooled = ctx @ out_w^T (k-split partials) ----------------
__global__ void k_pool(const float* __restrict__ ow) {
    const int f0 = blockIdx.x * 128;  // 8 tiles
    const int ks = blockIdx.y;        // 8
    const int tid = threadIdx.x;
    __shared__ float As[8][132];
    __shared__ float Bs[8][132];
    float acc[8][8];
    #pragma unroll
    for (int i = 0; i < 8; i++)
        #pragma unroll
        for (int j = 0; j < 8; j++) acc[i][j] = 0.f;
    const int lr = tid >> 1;
    const int lq = (tid & 1) * 4;
    const int ty = tid >> 4;
    const int tx = tid & 15;
    for (int k0 = ks * 128; k0 < ks * 128 + 128; k0 += 8) {
        float4 av = *(const float4*)&g_ctx[(size_t)lr * D_ + k0 + lq];
        float4 bv = *(const float4*)&ow[(size_t)(f0 + lr) * D_ + k0 + lq];
        __syncthreads();
        As[lq + 0][lr] = av.x; As[lq + 1][lr] = av.y; As[lq + 2][lr] = av.z; As[lq + 3][lr] = av.w;
        Bs[lq + 0][lr] = bv.x; Bs[lq + 1][lr] = bv.y; Bs[lq + 2][lr] = bv.z; Bs[lq + 3][lr] = bv.w;
        __syncthreads();
        #pragma unroll
        for (int kk = 0; kk < 8; kk++) {
            float a[8], bb[8];
            #pragma unroll
            for (int i = 0; i < 8; i++) a[i] = As[kk][ty * 8 + i];
            #pragma unroll
            for (int j = 0; j < 8; j++) bb[j] = Bs[kk][tx * 8 + j];
            #pragma unroll
            for (int i = 0; i < 8; i++)
                #pragma unroll
                for (int j = 0; j < 8; j++) acc[i][j] = fmaf(a[i], bb[j], acc[i][j]);
        }
    }
    #pragma unroll
    for (int i = 0; i < 8; i++) {
        int m = ty * 8 + i;
        float* dst = &g_poolp[ks][(size_t)m * D_ + f0 + tx * 8];
        *(float4*)dst = make_float4(acc[i][0], acc[i][1], acc[i][2], acc[i][3]);
        *(float4*)(dst + 4) = make_float4(acc[i][4], acc[i][5], acc[i][6], acc[i][7]);
    }
}

__global__ void k_poolred(const float* __restrict__ ob) {
    int idx = blockIdx.x * 256 + threadIdx.x;
    float s = ob[idx & 1023];
    #pragma unroll
    for (int ks = 0; ks < 8; ks++) s += g_poolp[ks][idx];
    g_pool[idx] = s;
}

// ---------------- K8: build summary rows, apply LayerNorms, write lnv/lng + mask ----------------
// cls mask: valid_mask[:,0] = (0 < len) = always true since len >= 1 -> constant 1.
__global__ void k_sum(const float* __restrict__ hid,
                      const float* __restrict__ qry,
                      const float* __restrict__ pg, const float* __restrict__ pb,
                      const float* __restrict__ vg, const float* __restrict__ vb,
                      const float* __restrict__ gg, const float* __restrict__ gb) {
    __shared__ float sh[8];
    const int row = blockIdx.x;
    const int tid = threadIdx.x;
    const int j = tid * 4;
    if (row >= NROW) {
        float4 z = make_float4(0.f, 0.f, 0.f, 0.f);
        *(float4*)&g_lnv[(size_t)row * D_ + j] = z;
        *(float4*)&g_lng[(size_t)row * D_ + j] = z;
        if (tid == 0) g_msk[row] = 0.f;
        return;
    }
    const int b = row / 73, t = row % 73;
    const int len = g_len[b];
    float x[4] = {0.f, 0.f, 0.f, 0.f};
    float msk = 0.f;
    bool ln1 = false;
    if (t == 0) {
        float4 v = *(const float4*)&hid[(size_t)b * S_ * D_ + j];
        x[0] = v.x; x[1] = v.y; x[2] = v.z; x[3] = v.w;
        msk = 1.f;    // len >= 1 always
    } else if (t < 9) {
        int p = t - 1;
        float4 qv = *(const float4*)&qry[(size_t)p * D_ + j];
        float4 pv = *(const float4*)&g_pool[(size_t)(b * P_ + p) * D_ + j];
        x[0] = qv.x + pv.x; x[1] = qv.y + pv.y; x[2] = qv.z + pv.z; x[3] = qv.w + pv.w;
        ln1 = true;
        msk = 1.f;
    } else {
        int s = len - 64 + (t - 9);
        if (s >= 1) {
            float4 v = *(const float4*)&hid[((size_t)b * S_ + s) * D_ + j];
            x[0] = v.x; x[1] = v.y; x[2] = v.z; x[3] = v.w;
            msk = 1.f;
        }
    }
    if (ln1) {   // pma rows: LN with ln_pma before the shared LNs
        float sm = blk_red_sum(x[0] + x[1] + x[2] + x[3], sh);
        float mu = sm * (1.f / (float)D_);
        float d0 = x[0] - mu, d1 = x[1] - mu, d2 = x[2] - mu, d3 = x[3] - mu;
        float vq = blk_red_sum(d0 * d0 + d1 * d1 + d2 * d2 + d3 * d3, sh);
        float inv = rsqrtf(vq * (1.f / (float)D_) + 1e-5f);
        #pragma unroll
        for (int c = 0; c < 4; c++) x[c] = (x[c] - mu) * inv * pg[j + c] + pb[j + c];
    }
    // second LN (shared stats for both output branches)
    float sm = blk_red_sum(x[0] + x[1] + x[2] + x[3], sh);
    float mu = sm * (1.f / (float)D_);
    float d0 = x[0] - mu, d1 = x[1] - mu, d2 = x[2] - mu, d3 = x[3] - mu;
    float vq = blk_red_sum(d0 * d0 + d1 * d1 + d2 * d2 + d3 * d3, sh);
    float inv = rsqrtf(vq * (1.f / (float)D_) + 1e-5f);
    float n0 = (x[0] - mu) * inv, n1 = (x[1] - mu) * inv, n2 = (x[2] - mu) * inv, n3 = (x[3] - mu) * inv;
    float4 ov = make_float4(n0 * vg[j] + vb[j], n1 * vg[j + 1] + vb[j + 1],
                            n2 * vg[j + 2] + vb[j + 2], n3 * vg[j + 3] + vb[j + 3]);
    float4 og = make_float4(n0 * gg[j] + gb[j], n1 * gg[j + 1] + gb[j + 1],
                            n2 * gg[j + 2] + gb[j + 2], n3 * gg[j + 3] + gb[j + 3]);
    *(float4*)&g_lnv[(size_t)row * D_ + j] = ov;
    *(float4*)&g_lng[(size_t)row * D_ + j] = og;
    if (tid == 0) g_msk[row] = msk;
}

// ---------------- K9: val/gate GEMMs (z=0: lnv@Wv^T+bv, z=1: lng@Wg^T+bg) ----------------
__global__ void __launch_bounds__(256, 2) k_vg(const float* __restrict__ wv, const float* __restrict__ bvv,
                     const float* __restrict__ wg, const float* __restrict__ bgg) {
    const int which = blockIdx.z;
    const int r0 = blockIdx.x * 128;   // 10 tiles over padded 1280 rows
    const int f0 = blockIdx.y * 128;   // 8 tiles
    const float* Am = which ? g_lng : g_lnv;
    const float* W = which ? wg : wv;
    const float* bias = which ? bgg : bvv;
    float* out = which ? g_graw : g_vraw;
    const int tid = threadIdx.x;
    __shared__ float As[8][132];
    __shared__ float Bs[8][132];
    float acc[8][8];
    #pragma unroll
    for (int i = 0; i < 8; i++)
        #pragma unroll
        for (int j = 0; j < 8; j++) acc[i][j] = 0.f;
    const int lr = tid >> 1;
    const int lq = (tid & 1) * 4;
    const int ty = tid >> 4;
    const int tx = tid & 15;
    for (int k0 = 0; k0 < D_; k0 += 8) {
        float4 av = *(const float4*)&Am[(size_t)(r0 + lr) * D_ + k0 + lq];
        float4 bv = *(const float4*)&W[(size_t)(f0 + lr) * D_ + k0 + lq];
        __syncthreads();
        As[lq + 0][lr] = av.x; As[lq + 1][lr] = av.y; As[lq + 2][lr] = av.z; As[lq + 3][lr] = av.w;
        Bs[lq + 0][lr] = bv.x; Bs[lq + 1][lr] = bv.y; Bs[lq + 2][lr] = bv.z; Bs[lq + 3][lr] = bv.w;
        __syncthreads();
        #pragma unroll
        for (int kk = 0; kk < 8; kk++) {
            float a[8], bb[8];
            #pragma unroll
            for (int i = 0; i < 8; i++) a[i] = As[kk][ty * 8 + i];
            #pragma unroll
            for (int j = 0; j < 8; j++) bb[j] = Bs[kk][tx * 8 + j];
            #pragma unroll
            for (int i = 0; i < 8; i++)
                #pragma unroll
                for (int j = 0; j < 8; j++) acc[i][j] = fmaf(a[i], bb[j], acc[i][j]);
        }
    }
    #pragma unroll
    for (int i = 0; i < 8; i++) {
        int r = r0 + ty * 8 + i;
        if (r >= NROW) continue;
        float o[8];
        #pragma unroll
        for (int j = 0; j < 8; j++) o[j] = acc[i][j] + bias[f0 + tx * 8 + j];
        float* dst = &out[(size_t)r * D_ + f0 + tx * 8];
        *(float4*)dst = make_float4(o[0], o[1], o[2], o[3]);
        *(float4*)(dst + 4) = make_float4(o[4], o[5], o[6], o[7]);
    }
}

// ---------------- K10: gated = silu(vraw)*sigmoid(graw)*mask -> output ----------------
__global__ void k_out(float* __restrict__ out, int write_mask) {
    int idx = blockIdx.x * 256 + threadIdx.x;
    if (idx < NROW * D_) {
        int row = idx >> 10;
        float v = g_vraw[idx], g = g_graw[idx];
        float sv = v / (1.f + expf(-v));       // silu
        float sg = 1.f / (1.f + expf(-g));     // sigmoid
        out[idx] = sv * sg * g_msk[row];
    }
    if (write_mask && idx < NROW) {
        out[NROW * D_ + idx] = g_msk[idx];
    }
}

// ---------------- host launcher ----------------
extern "C" void kernel_launch(void* const* d_in, const int* in_sizes, int n_in,
                              void* d_out, int out_size) {
    (void)in_sizes; (void)n_in;
    const float* hid = (const float*)d_in[0];
    const void*  vm  = d_in[1];
    const float* qry = (const float*)d_in[2];
    const float* ipw = (const float*)d_in[3];
    const float* ipb = (const float*)d_in[4];
    const float* ow  = (const float*)d_in[5];
    const float* ob  = (const float*)d_in[6];
    const float* pg  = (const float*)d_in[7];
    const float* pb  = (const float*)d_in[8];
    const float* vg  = (const float*)d_in[9];
    const float* vb  = (const float*)d_in[10];
    const float* Wv  = (const float*)d_in[11];
    const float* bv  = (const float*)d_in[12];
    const float* gg  = (const float*)d_in[13];
    const float* gb  = (const float*)d_in[14];
    const float* Wg  = (const float*)d_in[15];
    const float* bg  = (const float*)d_in[16];
    float* out = (float*)d_out;

    k_len<<<B_, 256>>>(vm);
    k_q<<<1024, 256>>>(qry, ipw, ipb);
    k_A<<<512, 256>>>(ipw);
    k_cb<<<1, 128>>>(ipb);
    k_scores<<<dim3(16, 16), 256>>>(hid);
    k_softmax<<<B_ * R_, 256>>>();
    k_ctxraw<<<dim3(8, 16), 256>>>(hid);
    k_ctx<<<dim3(16, 8), 256>>>(ipw);
    k_ctxred<<<512, 256>>>(ipb);
    k_pool<<<dim3(8, 8), 256>>>(ow);
    k_poolred<<<512, 256>>>(ob);
    k_sum<<<NROWP, 256>>>(hid, qry, pg, pb, vg, vb, gg, gb);
    k_vg<<<dim3(10, 8, 2), 256>>>(Wv, bv, Wg, bg);
    int wm = (out_size >= NROW * D_ + NROW) ? 1 : 0;
    k_out<<<(NROW * D_ + 255) / 256, 256>>>(out, wm);
}

// round 3
// speedup vs baseline: 2.8773x; 2.8773x over previous
#include <cuda_runtime.h>
#include <math.h>
#include <stdint.h>

#define B_    16
#define S_    2048
#define D_    1024
#define H_    16
#define P_    8
#define R_    128      // H_*P_
#define HD_   64
#define SUMN  73
#define NROW  1168     // B_*SUMN
#define NROWP 1280     // padded to 10*128

// ---------------- scratch (static device globals; no allocation) ----------------
__device__ int   g_len[B_];
__device__ float g_q[P_ * D_];
__device__ float g_A[R_ * D_];                    // tf32-rounded
__device__ float g_sc[(size_t)B_ * R_ * S_];      // scores -> attn (tf32-rounded after softmax)
__device__ float g_cr[(size_t)B_ * R_ * D_];      // ctxRaw [b][r=h*8+p][e]
__device__ float g_ctxp[8][R_ * D_];
__device__ float g_ctx[R_ * D_];
__device__ float g_poolp[8][R_ * D_];
__device__ float g_pool[R_ * D_];
__device__ float g_lnv[(size_t)NROWP * D_];       // tf32-rounded
__device__ float g_lng[(size_t)NROWP * D_];       // tf32-rounded
__device__ float g_wvt[D_ * D_];                  // tf32-rounded W_v
__device__ float g_wgt[D_ * D_];                  // tf32-rounded W_g
__device__ float g_vraw[(size_t)NROW * D_];
__device__ float g_graw[(size_t)NROW * D_];
__device__ float g_msk[NROWP];

// ---------------- helpers ----------------
__device__ __forceinline__ uint32_t cvt_tf32(float x) {
    uint32_t u; asm("cvt.rna.tf32.f32 %0, %1;" : "=r"(u) : "f"(x)); return u;
}
__device__ __forceinline__ float to_tf32f(float x) {
    uint32_t u; asm("cvt.rna.tf32.f32 %0, %1;" : "=r"(u) : "f"(x)); return __uint_as_float(u);
}
__device__ __forceinline__ uint32_t su(const void* p) {
    return (uint32_t)__cvta_generic_to_shared(p);
}
__device__ __forceinline__ void cpa16(uint32_t dst, const void* src) {
    asm volatile("cp.async.cg.shared.global [%0], [%1], 16;" :: "r"(dst), "l"(src));
}
#define CP_COMMIT() asm volatile("cp.async.commit_group;")
#define CP_WAIT1()  asm volatile("cp.async.wait_group 1;")

__device__ __forceinline__ void mma_tf32(float* d, const uint32_t* a, const uint32_t* b) {
    asm volatile(
        "mma.sync.aligned.m16n8k8.row.col.f32.tf32.tf32.f32 "
        "{%0,%1,%2,%3}, {%4,%5,%6,%7}, {%8,%9}, {%0,%1,%2,%3};"
        : "+f"(d[0]), "+f"(d[1]), "+f"(d[2]), "+f"(d[3])
        : "r"(a[0]), "r"(a[1]), "r"(a[2]), "r"(a[3]), "r"(b[0]), "r"(b[1]));
}

__device__ __forceinline__ float blk_red_sum(float v, float* sh) {
    #pragma unroll
    for (int o = 16; o > 0; o >>= 1) v += __shfl_down_sync(0xffffffffu, v, o);
    int w = threadIdx.x >> 5, l = threadIdx.x & 31;
    __syncthreads();
    if (l == 0) sh[w] = v;
    __syncthreads();
    float r = 0.f;
    #pragma unroll
    for (int i = 0; i < 8; i++) r += sh[i];
    return r;
}
__device__ __forceinline__ float blk_red_max(float v, float* sh) {
    #pragma unroll
    for (int o = 16; o > 0; o >>= 1) v = fmaxf(v, __shfl_down_sync(0xffffffffu, v, o));
    int w = threadIdx.x >> 5, l = threadIdx.x & 31;
    __syncthreads();
    if (l == 0) sh[w] = v;
    __syncthreads();
    float r = -3.4e38f;
    #pragma unroll
    for (int i = 0; i < 8; i++) r = fmaxf(r, sh[i]);
    return r;
}

// ---------------- K0: per-batch valid length (dtype-adaptive uint8/int32) ----------------
__global__ void k_len(const void* __restrict__ vmraw) {
    __shared__ int sh[256];
    __shared__ int is_u8;
    const unsigned char* vb = (const unsigned char*)vmraw;
    int b = blockIdx.x;
    if (threadIdx.x == 0) {
        int ones = 0;
        #pragma unroll
        for (int i = 0; i < 16; i++) ones += (vb[i] != 0) ? 1 : 0;
        is_u8 = (ones > 4) ? 1 : 0;
    }
    __syncthreads();
    int c = 0;
    if (is_u8) {
        for (int i = threadIdx.x; i < S_; i += 256)
            c += (vb[(size_t)b * S_ + i] != 0) ? 1 : 0;
    } else {
        const int* vi = (const int*)vmraw;
        for (int i = threadIdx.x; i < S_; i += 256)
            c += (vi[(size_t)b * S_ + i] != 0) ? 1 : 0;
    }
    sh[threadIdx.x] = c;
    __syncthreads();
    for (int o = 128; o > 0; o >>= 1) {
        if (threadIdx.x < o) sh[threadIdx.x] += sh[threadIdx.x + o];
        __syncthreads();
    }
    if (threadIdx.x == 0) g_len[b] = sh[0];
}

// ---------------- K1: q = queries @ Wq^T + bq ----------------
__global__ void k_q(const float* __restrict__ qry, const float* __restrict__ w,
                    const float* __restrict__ bia) {
    int wid = (blockIdx.x * 256 + threadIdx.x) >> 5;
    int l = threadIdx.x & 31;
    int p = wid >> 10;
    int j = wid & 1023;
    const float* qr = qry + (size_t)p * D_;
    const float* wr = w + (size_t)j * D_;
    float s = 0.f;
    for (int e = l; e < D_; e += 32) s += qr[e] * wr[e];
    #pragma unroll
    for (int o = 16; o > 0; o >>= 1) s += __shfl_down_sync(0xffffffffu, s, o);
    if (l == 0) g_q[p * D_ + j] = s + bia[j];
}

// ---------------- K2: A[r][e] = (1/8) * sum_d q[p][h*64+d] * Wk[h*64+d][e], tf32-rounded ----------------
// (per-row constant bias q.bk dropped: softmax is shift-invariant)
__global__ void k_A(const float* __restrict__ w) {
    int idx = blockIdx.x * 256 + threadIdx.x;
    int r = idx >> 10, e = idx & 1023;
    int h = r >> 3, p = r & 7;
    const float* qrow = g_q + p * D_ + h * HD_;
    const float* wr = w + (size_t)(D_ + h * HD_) * D_ + e;
    float s = 0.f;
    #pragma unroll 8
    for (int d = 0; d < HD_; d++) s += qrow[d] * wr[(size_t)d * D_];
    g_A[idx] = to_tf32f(0.125f * s);
}

// ---------------- K2b: preconvert W_v/W_g to tf32 ----------------
__global__ void k_cvtW(const float* __restrict__ wv, const float* __restrict__ wg) {
    int i = blockIdx.x * 256 + threadIdx.x;
    g_wvt[i] = to_tf32f(wv[i]);
    g_wgt[i] = to_tf32f(wg[i]);
}

// ---------------- K3: scores = hidden . A^T  (tensor tf32) ----------------
// M=128 (r), N=128 (s-tile), K=1024 (e). A=[m][k] tf32, B=hidden[s][e]=[n][k] (cvt at frag).
__global__ void __launch_bounds__(256, 2) k_scores_t(const float* __restrict__ hid) {
    const int b = blockIdx.y;
    const int s0 = blockIdx.x * 128;
    const int len = g_len[b];
    if (s0 >= len) return;
    __shared__ __align__(16) float sA[2][128][20];
    __shared__ __align__(16) float sB[2][128][20];
    const int tid = threadIdx.x;
    const int wid = tid >> 5, lane = tid & 31;
    const int g = lane >> 2, c = lane & 3;
    const int m0 = (wid >> 2) * 64, n0 = (wid & 3) * 32;
    const float* hb = hid + (size_t)b * S_ * D_;
    float acc[4][4][4];
    #pragma unroll
    for (int i = 0; i < 4; i++) for (int j = 0; j < 4; j++) for (int k = 0; k < 4; k++) acc[i][j][k] = 0.f;

#define SC_LOAD(T, BUF) { \
        int kg = (T) * 16; \
        for (int q = tid; q < 512; q += 256) { \
            int row = q >> 2, cc = q & 3; \
            cpa16(su(&sA[BUF][row][cc * 4]), g_A + (size_t)row * D_ + kg + cc * 4); \
        } \
        for (int q = tid; q < 512; q += 256) { \
            int row = q >> 2, cc = q & 3; \
            cpa16(su(&sB[BUF][row][cc * 4]), hb + (size_t)(s0 + row) * D_ + kg + cc * 4); \
        } }

    SC_LOAD(0, 0); CP_COMMIT();
    for (int t = 0; t < 64; t++) {
        int cur = t & 1;
        if (t + 1 < 64) { SC_LOAD(t + 1, cur ^ 1); }
        CP_COMMIT();
        CP_WAIT1();
        __syncthreads();
        #pragma unroll
        for (int kk = 0; kk < 2; kk++) {
            int kb = kk * 8;
            uint32_t A4[4][4], B2[4][2];
            #pragma unroll
            for (int i = 0; i < 4; i++) {
                A4[i][0] = __float_as_uint(sA[cur][m0 + i * 16 + g][kb + c]);
                A4[i][1] = __float_as_uint(sA[cur][m0 + i * 16 + g + 8][kb + c]);
                A4[i][2] = __float_as_uint(sA[cur][m0 + i * 16 + g][kb + c + 4]);
                A4[i][3] = __float_as_uint(sA[cur][m0 + i * 16 + g + 8][kb + c + 4]);
            }
            #pragma unroll
            for (int j = 0; j < 4; j++) {
                B2[j][0] = cvt_tf32(sB[cur][n0 + j * 8 + g][kb + c]);
                B2[j][1] = cvt_tf32(sB[cur][n0 + j * 8 + g][kb + c + 4]);
            }
            #pragma unroll
            for (int i = 0; i < 4; i++)
                #pragma unroll
                for (int j = 0; j < 4; j++) mma_tf32(acc[i][j], A4[i], B2[j]);
        }
        __syncthreads();
    }
#undef SC_LOAD
    #pragma unroll
    for (int i = 0; i < 4; i++)
        #pragma unroll
        for (int j = 0; j < 4; j++) {
            int r = m0 + i * 16 + g;
            int s = s0 + n0 + j * 8 + 2 * c;
            float* p0 = &g_sc[((size_t)(b * R_ + r)) * S_ + s];
            *(float2*)p0 = make_float2(acc[i][j][0], acc[i][j][1]);
            *(float2*)(p0 + 8 * S_) = make_float2(acc[i][j][2], acc[i][j][3]);
        }
}

// ---------------- K4: softmax over s<len per (b,r) row; rounds attn to tf32; zero-fills tail ----------------
__global__ void k_softmax() {
    __shared__ float sh[8];
    int row = blockIdx.x;
    int b = row >> 7;
    int len = g_len[b];
    size_t base = (size_t)row * S_;
    int tid = threadIdx.x;
    float v[8];
    int n = 0;
    float mx = -3.4e38f;
    for (int i = tid; i < len; i += 256) { float x = g_sc[base + i]; v[n++] = x; mx = fmaxf(mx, x); }
    float bm = blk_red_max(mx, sh);
    float s = 0.f;
    for (int k = 0; k < n; k++) { v[k] = expf(v[k] - bm); s += v[k]; }
    float bs = blk_red_sum(s, sh);
    float inv = 1.f / bs;
    n = 0;
    for (int i = tid; i < len; i += 256) g_sc[base + i] = to_tf32f(v[n++] * inv);
    int rend = (len + 127) & ~127;
    for (int i = len + tid; i < rend; i += 256) g_sc[base + i] = 0.f;
}

// ---------------- K5: ctxRaw = attn . hidden  (tensor tf32, K=len masked) ----------------
// M=128 (r), N=128 (e-tile), K=s. A=attn[r][s]=[m][k] tf32, B=hidden[s][e]=[k][n] (cvt at frag).
__global__ void __launch_bounds__(256, 2) k_ctxraw_t(const float* __restrict__ hid) {
    const int b = blockIdx.y;
    const int e0 = blockIdx.x * 128;
    const int len = g_len[b];
    const int NT = (len + 15) >> 4;
    __shared__ __align__(16) float sA[2][128][20];
    __shared__ __align__(16) float sB[2][16][132];
    const int tid = threadIdx.x;
    const int wid = tid >> 5, lane = tid & 31;
    const int g = lane >> 2, c = lane & 3;
    const int m0 = (wid >> 2) * 64, n0 = (wid & 3) * 32;
    const float* hb = hid + (size_t)b * S_ * D_;
    float acc[4][4][4];
    #pragma unroll
    for (int i = 0; i < 4; i++) for (int j = 0; j < 4; j++) for (int k = 0; k < 4; k++) acc[i][j][k] = 0.f;

#define CR_LOAD(T, BUF) { \
        int kg = (T) * 16; \
        for (int q = tid; q < 512; q += 256) { \
            int row = q >> 2, cc = q & 3; \
            cpa16(su(&sA[BUF][row][cc * 4]), g_sc + ((size_t)(b * R_ + row)) * S_ + kg + cc * 4); \
        } \
        for (int q = tid; q < 512; q += 256) { \
            int row = q >> 5, cc = q & 31; \
            cpa16(su(&sB[BUF][row][cc * 4]), hb + (size_t)(kg + row) * D_ + e0 + cc * 4); \
        } }

    CR_LOAD(0, 0); CP_COMMIT();
    for (int t = 0; t < NT; t++) {
        int cur = t & 1;
        if (t + 1 < NT) { CR_LOAD(t + 1, cur ^ 1); }
        CP_COMMIT();
        CP_WAIT1();
        __syncthreads();
        #pragma unroll
        for (int kk = 0; kk < 2; kk++) {
            int kb = kk * 8;
            uint32_t A4[4][4], B2[4][2];
            #pragma unroll
            for (int i = 0; i < 4; i++) {
                A4[i][0] = __float_as_uint(sA[cur][m0 + i * 16 + g][kb + c]);
                A4[i][1] = __float_as_uint(sA[cur][m0 + i * 16 + g + 8][kb + c]);
                A4[i][2] = __float_as_uint(sA[cur][m0 + i * 16 + g][kb + c + 4]);
                A4[i][3] = __float_as_uint(sA[cur][m0 + i * 16 + g + 8][kb + c + 4]);
            }
            #pragma unroll
            for (int j = 0; j < 4; j++) {
                B2[j][0] = cvt_tf32(sB[cur][kb + c][n0 + j * 8 + g]);
                B2[j][1] = cvt_tf32(sB[cur][kb + c + 4][n0 + j * 8 + g]);
            }
            #pragma unroll
            for (int i = 0; i < 4; i++)
                #pragma unroll
                for (int j = 0; j < 4; j++) mma_tf32(acc[i][j], A4[i], B2[j]);
        }
        __syncthreads();
    }
#undef CR_LOAD
    #pragma unroll
    for (int i = 0; i < 4; i++)
        #pragma unroll
        for (int j = 0; j < 4; j++) {
            int r = m0 + i * 16 + g;
            int e = e0 + n0 + j * 8 + 2 * c;
            float* p0 = &g_cr[((size_t)(b * R_ + r)) * D_ + e];
            *(float2*)p0 = make_float2(acc[i][j][0], acc[i][j][1]);
            *(float2*)(p0 + 8 * D_) = make_float2(acc[i][j][2], acc[i][j][3]);
        }
}

// ---------------- K6: ctx per head (FFMA k-split; small) ----------------
__global__ void k_ctx(const float* __restrict__ w) {
    const int h = blockIdx.x;
    const int ks = blockIdx.y;
    const int tid = threadIdx.x;
    __shared__ float As[8][132];
    __shared__ float Bs[8][68];
    float acc[8][4];
    #pragma unroll
    for (int i = 0; i < 8; i++) for (int j = 0; j < 4; j++) acc[i][j] = 0.f;
    const int lm = tid >> 1;
    const int lq = (tid & 1) * 4;
    const int ln_ = tid >> 2;
    const int lq2 = (tid & 3) * 2;
    const int ty = tid >> 4;
    const int tx = tid & 15;
    const int bA = lm >> 3, pA = lm & 7;
    const size_t arow = ((size_t)(bA * R_ + h * P_ + pA)) * D_;
    const size_t wrow = (size_t)(2 * D_ + h * HD_ + ln_) * D_;
    for (int k0 = ks * 128; k0 < ks * 128 + 128; k0 += 8) {
        float4 av = *(const float4*)&g_cr[arow + k0 + lq];
        float2 wv = *(const float2*)&w[wrow + k0 + lq2];
        __syncthreads();
        As[lq + 0][lm] = av.x; As[lq + 1][lm] = av.y; As[lq + 2][lm] = av.z; As[lq + 3][lm] = av.w;
        Bs[lq2 + 0][ln_] = wv.x; Bs[lq2 + 1][ln_] = wv.y;
        __syncthreads();
        #pragma unroll
        for (int kk = 0; kk < 8; kk++) {
            float a[8], bb[4];
            #pragma unroll
            for (int i = 0; i < 8; i++) a[i] = As[kk][ty * 8 + i];
            #pragma unroll
            for (int j = 0; j < 4; j++) bb[j] = Bs[kk][tx * 4 + j];
            #pragma unroll
            for (int i = 0; i < 8; i++)
                #pragma unroll
                for (int j = 0; j < 4; j++) acc[i][j] = fmaf(a[i], bb[j], acc[i][j]);
        }
    }
    #pragma unroll
    for (int i = 0; i < 8; i++) {
        int m = ty * 8 + i;
        *(float4*)&g_ctxp[ks][(size_t)m * D_ + h * HD_ + tx * 4] =
            make_float4(acc[i][0], acc[i][1], acc[i][2], acc[i][3]);
    }
}

__global__ void k_ctxred(const float* __restrict__ ipb) {
    int idx = blockIdx.x * 256 + threadIdx.x;
    float s = ipb[2 * D_ + (idx & 1023)];
    #pragma unroll
    for (int ks = 0; ks < 8; ks++) s += g_ctxp[ks][idx];
    g_ctx[idx] = s;
}

// ---------------- K7: pooled = ctx @ out_w^T (FFMA k-split; small) ----------------
__global__ void k_pool(const float* __restrict__ ow) {
    const int f0 = blockIdx.x * 128;
    const int ks = blockIdx.y;
    const int tid = threadIdx.x;
    __shared__ float As[8][132];
    __shared__ float Bs[8][132];
    float acc[8][8];
    #pragma unroll
    for (int i = 0; i < 8; i++) for (int j = 0; j < 8; j++) acc[i][j] = 0.f;
    const int lr = tid >> 1;
    const int lq = (tid & 1) * 4;
    const int ty = tid >> 4;
    const int tx = tid & 15;
    for (int k0 = ks * 128; k0 < ks * 128 + 128; k0 += 8) {
        float4 av = *(const float4*)&g_ctx[(size_t)lr * D_ + k0 + lq];
        float4 bv = *(const float4*)&ow[(size_t)(f0 + lr) * D_ + k0 + lq];
        __syncthreads();
        As[lq + 0][lr] = av.x; As[lq + 1][lr] = av.y; As[lq + 2][lr] = av.z; As[lq + 3][lr] = av.w;
        Bs[lq + 0][lr] = bv.x; Bs[lq + 1][lr] = bv.y; Bs[lq + 2][lr] = bv.z; Bs[lq + 3][lr] = bv.w;
        __syncthreads();
        #pragma unroll
        for (int kk = 0; kk < 8; kk++) {
            float a[8], bb[8];
            #pragma unroll
            for (int i = 0; i < 8; i++) a[i] = As[kk][ty * 8 + i];
            #pragma unroll
            for (int j = 0; j < 8; j++) bb[j] = Bs[kk][tx * 8 + j];
            #pragma unroll
            for (int i = 0; i < 8; i++)
                #pragma unroll
                for (int j = 0; j < 8; j++) acc[i][j] = fmaf(a[i], bb[j], acc[i][j]);
        }
    }
    #pragma unroll
    for (int i = 0; i < 8; i++) {
        int m = ty * 8 + i;
        float* dst = &g_poolp[ks][(size_t)m * D_ + f0 + tx * 8];
        *(float4*)dst = make_float4(acc[i][0], acc[i][1], acc[i][2], acc[i][3]);
        *(float4*)(dst + 4) = make_float4(acc[i][4], acc[i][5], acc[i][6], acc[i][7]);
    }
}

__global__ void k_poolred(const float* __restrict__ ob) {
    int idx = blockIdx.x * 256 + threadIdx.x;
    float s = ob[idx & 1023];
    #pragma unroll
    for (int ks = 0; ks < 8; ks++) s += g_poolp[ks][idx];
    g_pool[idx] = s;
}

// ---------------- K8: build summary rows, LayerNorms, write tf32-rounded lnv/lng + mask ----------------
__global__ void k_sum(const float* __restrict__ hid,
                      const float* __restrict__ qry,
                      const float* __restrict__ pg, const float* __restrict__ pb,
                      const float* __restrict__ vg, const float* __restrict__ vb,
                      const float* __restrict__ gg, const float* __restrict__ gb) {
    __shared__ float sh[8];
    const int row = blockIdx.x;
    const int tid = threadIdx.x;
    const int j = tid * 4;
    if (row >= NROW) {
        float4 z = make_float4(0.f, 0.f, 0.f, 0.f);
        *(float4*)&g_lnv[(size_t)row * D_ + j] = z;
        *(float4*)&g_lng[(size_t)row * D_ + j] = z;
        if (tid == 0) g_msk[row] = 0.f;
        return;
    }
    const int b = row / 73, t = row % 73;
    const int len = g_len[b];
    float x[4] = {0.f, 0.f, 0.f, 0.f};
    float msk = 0.f;
    bool ln1 = false;
    if (t == 0) {
        float4 v = *(const float4*)&hid[(size_t)b * S_ * D_ + j];
        x[0] = v.x; x[1] = v.y; x[2] = v.z; x[3] = v.w;
        msk = 1.f;
    } else if (t < 9) {
        int p = t - 1;
        float4 qv = *(const float4*)&qry[(size_t)p * D_ + j];
        float4 pv = *(const float4*)&g_pool[(size_t)(b * P_ + p) * D_ + j];
        x[0] = qv.x + pv.x; x[1] = qv.y + pv.y; x[2] = qv.z + pv.z; x[3] = qv.w + pv.w;
        ln1 = true;
        msk = 1.f;
    } else {
        int s = len - 64 + (t - 9);
        if (s >= 1) {
            float4 v = *(const float4*)&hid[((size_t)b * S_ + s) * D_ + j];
            x[0] = v.x; x[1] = v.y; x[2] = v.z; x[3] = v.w;
            msk = 1.f;
        }
    }
    if (ln1) {
        float sm = blk_red_sum(x[0] + x[1] + x[2] + x[3], sh);
        float mu = sm * (1.f / (float)D_);
        float d0 = x[0] - mu, d1 = x[1] - mu, d2 = x[2] - mu, d3 = x[3] - mu;
        float vq = blk_red_sum(d0 * d0 + d1 * d1 + d2 * d2 + d3 * d3, sh);
        float inv = rsqrtf(vq * (1.f / (float)D_) + 1e-5f);
        #pragma unroll
        for (int c = 0; c < 4; c++) x[c] = (x[c] - mu) * inv * pg[j + c] + pb[j + c];
    }
    float sm = blk_red_sum(x[0] + x[1] + x[2] + x[3], sh);
    float mu = sm * (1.f / (float)D_);
    float d0 = x[0] - mu, d1 = x[1] - mu, d2 = x[2] - mu, d3 = x[3] - mu;
    float vq = blk_red_sum(d0 * d0 + d1 * d1 + d2 * d2 + d3 * d3, sh);
    float inv = rsqrtf(vq * (1.f / (float)D_) + 1e-5f);
    float n0 = (x[0] - mu) * inv, n1 = (x[1] - mu) * inv, n2 = (x[2] - mu) * inv, n3 = (x[3] - mu) * inv;
    float4 ov = make_float4(to_tf32f(n0 * vg[j] + vb[j]), to_tf32f(n1 * vg[j + 1] + vb[j + 1]),
                            to_tf32f(n2 * vg[j + 2] + vb[j + 2]), to_tf32f(n3 * vg[j + 3] + vb[j + 3]));
    float4 og = make_float4(to_tf32f(n0 * gg[j] + gb[j]), to_tf32f(n1 * gg[j + 1] + gb[j + 1]),
                            to_tf32f(n2 * gg[j + 2] + gb[j + 2]), to_tf32f(n3 * gg[j + 3] + gb[j + 3]));
    *(float4*)&g_lnv[(size_t)row * D_ + j] = ov;
    *(float4*)&g_lng[(size_t)row * D_ + j] = og;
    if (tid == 0) g_msk[row] = msk;
}

// ---------------- K9: val/gate GEMMs (tensor tf32; z=0: lnv@Wv^T+bv, z=1: lng@Wg^T+bg) ----------------
__global__ void __launch_bounds__(256, 2) k_vg_t(const float* __restrict__ bvv, const float* __restrict__ bgg) {
    const int which = blockIdx.z;
    const int r0 = blockIdx.x * 128;
    const int f0 = blockIdx.y * 128;
    const float* Am = which ? g_lng : g_lnv;
    const float* W  = which ? g_wgt : g_wvt;
    const float* bias = which ? bgg : bvv;
    float* out = which ? g_graw : g_vraw;
    __shared__ __align__(16) float sA[2][128][20];
    __shared__ __align__(16) float sB[2][128][20];
    const int tid = threadIdx.x;
    const int wid = tid >> 5, lane = tid & 31;
    const int g = lane >> 2, c = lane & 3;
    const int m0 = (wid >> 2) * 64, n0 = (wid & 3) * 32;
    float acc[4][4][4];
    #pragma unroll
    for (int i = 0; i < 4; i++) for (int j = 0; j < 4; j++) for (int k = 0; k < 4; k++) acc[i][j][k] = 0.f;

#define VG_LOAD(T, BUF) { \
        int kg = (T) * 16; \
        for (int q = tid; q < 512; q += 256) { \
            int row = q >> 2, cc = q & 3; \
            cpa16(su(&sA[BUF][row][cc * 4]), Am + (size_t)(r0 + row) * D_ + kg + cc * 4); \
        } \
        for (int q = tid; q < 512; q += 256) { \
            int row = q >> 2, cc = q & 3; \
            cpa16(su(&sB[BUF][row][cc * 4]), W + (size_t)(f0 + row) * D_ + kg + cc * 4); \
        } }

    VG_LOAD(0, 0); CP_COMMIT();
    for (int t = 0; t < 64; t++) {
        int cur = t & 1;
        if (t + 1 < 64) { VG_LOAD(t + 1, cur ^ 1); }
        CP_COMMIT();
        CP_WAIT1();
        __syncthreads();
        #pragma unroll
        for (int kk = 0; kk < 2; kk++) {
            int kb = kk * 8;
            uint32_t A4[4][4], B2[4][2];
            #pragma unroll
            for (int i = 0; i < 4; i++) {
                A4[i][0] = __float_as_uint(sA[cur][m0 + i * 16 + g][kb + c]);
                A4[i][1] = __float_as_uint(sA[cur][m0 + i * 16 + g + 8][kb + c]);
                A4[i][2] = __float_as_uint(sA[cur][m0 + i * 16 + g][kb + c + 4]);
                A4[i][3] = __float_as_uint(sA[cur][m0 + i * 16 + g + 8][kb + c + 4]);
            }
            #pragma unroll
            for (int j = 0; j < 4; j++) {
                B2[j][0] = __float_as_uint(sB[cur][n0 + j * 8 + g][kb + c]);
                B2[j][1] = __float_as_uint(sB[cur][n0 + j * 8 + g][kb + c + 4]);
            }
            #pragma unroll
            for (int i = 0; i < 4; i++)
                #pragma unroll
                for (int j = 0; j < 4; j++) mma_tf32(acc[i][j], A4[i], B2[j]);
        }
        __syncthreads();
    }
#undef VG_LOAD
    #pragma unroll
    for (int i = 0; i < 4; i++)
        #pragma unroll
        for (int j = 0; j < 4; j++) {
            int f = f0 + n0 + j * 8 + 2 * c;
            float b0 = bias[f], b1 = bias[f + 1];
            int r = r0 + m0 + i * 16 + g;
            if (r < NROW)
                *(float2*)&out[(size_t)r * D_ + f] = make_float2(acc[i][j][0] + b0, acc[i][j][1] + b1);
            if (r + 8 < NROW)
                *(float2*)&out[(size_t)(r + 8) * D_ + f] = make_float2(acc[i][j][2] + b0, acc[i][j][3] + b1);
        }
}

// ---------------- K10: gated = silu(vraw)*sigmoid(graw)*mask -> output ----------------
__global__ void k_out(float* __restrict__ out, int write_mask) {
    int idx = blockIdx.x * 256 + threadIdx.x;
    if (idx < NROW * D_) {
        int row = idx >> 10;
        float v = g_vraw[idx], g = g_graw[idx];
        float sv = v / (1.f + expf(-v));
        float sg = 1.f / (1.f + expf(-g));
        out[idx] = sv * sg * g_msk[row];
    }
    if (write_mask && idx < NROW) {
        out[NROW * D_ + idx] = g_msk[idx];
    }
}

// ---------------- host launcher ----------------
extern "C" void kernel_launch(void* const* d_in, const int* in_sizes, int n_in,
                              void* d_out, int out_size) {
    (void)in_sizes; (void)n_in;
    const float* hid = (const float*)d_in[0];
    const void*  vm  = d_in[1];
    const float* qry = (const float*)d_in[2];
    const float* ipw = (const float*)d_in[3];
    const float* ipb = (const float*)d_in[4];
    const float* ow  = (const float*)d_in[5];
    const float* ob  = (const float*)d_in[6];
    const float* pg  = (const float*)d_in[7];
    const float* pb  = (const float*)d_in[8];
    const float* vg  = (const float*)d_in[9];
    const float* vb  = (const float*)d_in[10];
    const float* Wv  = (const float*)d_in[11];
    const float* bv  = (const float*)d_in[12];
    const float* gg  = (const float*)d_in[13];
    const float* gb  = (const float*)d_in[14];
    const float* Wg  = (const float*)d_in[15];
    const float* bg  = (const float*)d_in[16];
    float* out = (float*)d_out;

    k_len<<<B_, 256>>>(vm);
    k_q<<<1024, 256>>>(qry, ipw, ipb);
    k_A<<<512, 256>>>(ipw);
    k_cvtW<<<4096, 256>>>(Wv, Wg);
    k_scores_t<<<dim3(16, 16), 256>>>(hid);
    k_softmax<<<B_ * R_, 256>>>();
    k_ctxraw_t<<<dim3(8, 16), 256>>>(hid);
    k_ctx<<<dim3(16, 8), 256>>>(ipw);
    k_ctxred<<<512, 256>>>(ipb);
    k_pool<<<dim3(8, 8), 256>>>(ow);
    k_poolred<<<512, 256>>>(ob);
    k_sum<<<NROWP, 256>>>(hid, qry, pg, pb, vg, vb, gg, gb);
    k_vg_t<<<dim3(10, 8, 2), 256>>>(bv, bg);
    int wm = (out_size >= NROW * D_ + NROW) ? 1 : 0;
    k_out<<<(NROW * D_ + 255) / 256, 256>>>(out, wm);
}